// round 2
// baseline (speedup 1.0000x reference)
#include <cuda_runtime.h>
#include <math.h>

// ---------------------------------------------------------------------------
// Problem constants (all shapes static):
//   C=64 channels, unfold into 10x10x10 pixel-shuffle blocks -> M = 64*1000 rows.
//   Branch dims: axi d=140 (w=5,7,4), cor d=112 (w=4,4,7), sag d=160 (w=4,8,5).
//   atlas0: 64000 x 120 (w=5,6,4).
// Algebra: S = Wq^T G Wk + (Wq^T sA) bk^T + bq (sB^T Wk) + M bq bk^T,  G = A^T B
//          P = softmax_rows(S);  cross = B (Wv P^T) + 1 (P bv)^T
// ---------------------------------------------------------------------------

#define M_TOTAL 64000

__device__ float g_atlas0[64000*120];
__device__ float g_A[64000*160];
__device__ float g_B[64000*160];
__device__ float g_G[160*160];
__device__ float g_T[160*160];
__device__ float g_S[160*160];
__device__ float g_U[160*160];
__device__ float g_sA[160];
__device__ float g_sB[160];
__device__ float g_Z[160];
__device__ float g_pb[160];

template<int BR> struct Cfg;
// axi: input (64,48,66,38) direct; pad->(50,70,40) pb(1,2,1); w=(5,7,4); D=140
template<> struct Cfg<0>{
  static constexpr int D=140, W0=5,W1=7,W2=4, P0=1,P1=2,P2=1, I0=48,I1=66,I2=38;
  static constexpr int OUT0=0;
};
// cor: internal = cor.transpose(0,1,2,4,3) -> (64,38,38,66); pb(1,1,2); w=(4,4,7); D=112
template<> struct Cfg<1>{
  static constexpr int D=112, W0=4,W1=4,W2=7, P0=1,P1=1,P2=2, I0=38,I1=38,I2=66;
  static constexpr int OUT0=7704576;
};
// sag: internal = sag.transpose(0,1,4,3,2) -> (64,38,78,48); pb(1,1,1); w=(4,8,5); D=160
template<> struct Cfg<2>{
  static constexpr int D=160, W0=4,W1=8,W2=5, P0=1,P1=1,P2=1, I0=38,I1=78,I2=48;
  static constexpr int OUT0=13804032;
};

// gather from raw input, folding the branch transpose; 0 outside valid region
template<int BR>
__device__ __forceinline__ float loadFeat(const float* __restrict__ f, int cc, int z, int y, int x){
  if ((unsigned)z >= (unsigned)Cfg<BR>::I0 ||
      (unsigned)y >= (unsigned)Cfg<BR>::I1 ||
      (unsigned)x >= (unsigned)Cfg<BR>::I2) return 0.f;
  if constexpr (BR==0) return f[((cc*48+z)*66+y)*38+x];
  else if constexpr (BR==1) return f[((cc*38+z)*66+x)*38+y];
  else                      return f[((cc*48+x)*78+y)*38+z];
}

// scatter index into concatenated output, folding inverse branch transpose
template<int BR>
__device__ __forceinline__ int outIndex(int cc, int z, int y, int x){
  if constexpr (BR==0) return ((cc*48+z)*66+y)*38+x;
  else if constexpr (BR==1) return Cfg<1>::OUT0 + ((cc*38+z)*66+x)*38+y;
  else                      return Cfg<2>::OUT0 + ((cc*48+x)*78+y)*38+z;
}

// composed nearest-neighbor index chain: branch spatial col -> atlas0 col (5,6,4 grid)
template<int BR>
__device__ __forceinline__ int atlasCol(int j){
  if constexpr (BR==0){
    int z=j/28, y=(j/4)%7, x=j%4;            // (5,7,4)
    int y0=(y*6)/7;
    return (z*6+y0)*4+x;
  } else if constexpr (BR==1){
    int z=j/28, y=(j/7)%4, x=j%7;            // (4,4,7) <- (5,7,4)
    int z1=(z*5)/4, y1=(y*7)/4, x1=(x*4)/7;
    int y0=(y1*6)/7;
    return (z1*6+y0)*4+x1;
  } else {
    int z=j/40, y=(j/5)%8, x=j%5;            // (4,8,5) <- (4,4,7) <- (5,7,4)
    int z2=z,  y2=y/2,     x2=(x*7)/5;
    int z1=(z2*5)/4, y1=(y2*7)/4, x1=(x2*4)/7;
    int y0=(y1*6)/7;
    return (z1*6+y0)*4+x1;
  }
}

// ---------------- kernels ----------------

__global__ void zero_small(){
  int t = blockIdx.x*256 + threadIdx.x;
  if (t < 160*160) g_G[t] = 0.f;
  if (t < 160){ g_sA[t]=0.f; g_sB[t]=0.f; }
}

__global__ void build_atlas0(const float* __restrict__ atlas){
  int idx = blockIdx.x*256 + threadIdx.x;
  if (idx >= 64000*120) return;
  int m = idx / 120, j = idx % 120;
  int cc = m / 1000, r = m % 1000;
  int a0 = r/100, a1 = (r/10)%10, a2 = r%10;
  int b0 = j/24, b1 = (j/4)%6, b2 = j%4;
  int z = a0*5 + b0 - 2, y = a1*6 + b1 - 2, x = a2*4 + b2 - 1;
  float v = 0.f;
  if ((unsigned)z < 46u && (unsigned)y < 56u && (unsigned)x < 38u)
    v = atlas[((cc*46+z)*56+y)*38+x];
  g_atlas0[idx] = v;
}

template<int BR>
__global__ void build_A(){
  constexpr int D = Cfg<BR>::D;
  int idx = blockIdx.x*256 + threadIdx.x;
  if (idx >= 64000*D) return;
  int m = idx / D, i = idx % D;
  g_A[idx] = g_atlas0[m*120 + atlasCol<BR>(i)];
}

template<int BR>
__global__ void build_B(const float* __restrict__ feat){
  constexpr int D = Cfg<BR>::D;
  int idx = blockIdx.x*256 + threadIdx.x;
  if (idx >= 64000*D) return;
  int m = idx / D, j = idx % D;
  int cc = m/1000, r = m%1000;
  int a0 = r/100, a1 = (r/10)%10, a2 = r%10;
  int b0 = j/(Cfg<BR>::W1*Cfg<BR>::W2), b1 = (j/Cfg<BR>::W2)%Cfg<BR>::W1, b2 = j%Cfg<BR>::W2;
  int z = a0*Cfg<BR>::W0 + b0 - Cfg<BR>::P0;
  int y = a1*Cfg<BR>::W1 + b1 - Cfg<BR>::P1;
  int x = a2*Cfg<BR>::W2 + b2 - Cfg<BR>::P2;
  g_B[idx] = loadFeat<BR>(feat, cc, z, y, x);
}

// G = A^T B (DxD, K=64000), split-K with atomic reduction; fused column sums
template<int D, int CHUNK>
__global__ void __launch_bounds__(256) gemmG(){
  __shared__ float As[16][64];
  __shared__ float Bs[16][64];
  int tj0 = blockIdx.x*64, ti0 = blockIdx.y*64;
  int m0  = blockIdx.z*CHUNK;
  int t = threadIdx.x;
  int lc = t & 63, lr = t >> 6;    // loader: column, row-group
  int tx = t & 15, ty = t >> 4;    // compute: 4x4 per thread
  float acc[4][4];
  #pragma unroll
  for (int u=0;u<4;u++)
    #pragma unroll
    for (int v=0;v<4;v++) acc[u][v]=0.f;
  float aColSum = 0.f, bColSum = 0.f;

  for (int mc = 0; mc < CHUNK; mc += 16){
    #pragma unroll
    for (int s=0;s<4;s++){
      int kk = lr + 4*s;
      int row = m0 + mc + kk;
      float a = (ti0+lc < D) ? g_A[row*D + ti0 + lc] : 0.f;
      float b = (tj0+lc < D) ? g_B[row*D + tj0 + lc] : 0.f;
      As[kk][lc] = a; Bs[kk][lc] = b;
      aColSum += a; bColSum += b;
    }
    __syncthreads();
    #pragma unroll
    for (int kk=0;kk<16;kk++){
      float4 a4 = *reinterpret_cast<const float4*>(&As[kk][ty*4]);
      float4 b4 = *reinterpret_cast<const float4*>(&Bs[kk][tx*4]);
      float av[4]={a4.x,a4.y,a4.z,a4.w};
      float bv[4]={b4.x,b4.y,b4.z,b4.w};
      #pragma unroll
      for (int u=0;u<4;u++)
        #pragma unroll
        for (int v=0;v<4;v++) acc[u][v] += av[u]*bv[v];
    }
    __syncthreads();
  }
  #pragma unroll
  for (int u=0;u<4;u++){
    int i = ti0 + ty*4 + u;
    if (i < D){
      #pragma unroll
      for (int v=0;v<4;v++){
        int j = tj0 + tx*4 + v;
        if (j < D) atomicAdd(&g_G[i*D+j], acc[u][v]);
      }
    }
  }
  if (blockIdx.x==0 && ti0+lc < D) atomicAdd(&g_sA[ti0+lc], aColSum);
  if (blockIdx.y==0 && tj0+lc < D) atomicAdd(&g_sB[tj0+lc], bColSum);
}

// T = G*Wk ; Z[j] = sB.Wk[:,j] + M*bk[j]
template<int D>
__global__ void smallT(const float* __restrict__ Wk, const float* __restrict__ bk){
  int idx = blockIdx.x*256 + threadIdx.x;
  if (idx < D*D){
    int p = idx/D, j = idx%D;
    float acc = 0.f;
    for (int r=0;r<D;r++) acc += g_G[p*D+r]*Wk[r*D+j];
    g_T[idx] = acc;
  }
  if (idx < D){
    float z = 0.f;
    for (int r=0;r<D;r++) z += g_sB[r]*Wk[r*D+idx];
    g_Z[idx] = z + 64000.f*bk[idx];
  }
}

// S = Wq^T T + (Wq^T sA) bk^T + bq Z^T
template<int D>
__global__ void smallS(const float* __restrict__ Wq, const float* __restrict__ bq,
                       const float* __restrict__ bk){
  int idx = blockIdx.x*256 + threadIdx.x;
  if (idx >= D*D) return;
  int i = idx/D, j = idx%D;
  float acc = 0.f, acc2 = 0.f;
  for (int p=0;p<D;p++){
    float w = Wq[p*D+i];
    acc  += w * g_T[p*D+j];
    acc2 += w * g_sA[p];
  }
  g_S[idx] = acc + acc2*bk[j] + bq[i]*g_Z[j];
}

template<int D>
__global__ void softmaxK(){
  __shared__ float red[256];
  int i = blockIdx.x, t = threadIdx.x;
  float v = (t < D) ? g_S[i*D+t] : -3.4e38f;
  red[t] = v; __syncthreads();
  for (int s=128; s>0; s>>=1){ if (t<s) red[t]=fmaxf(red[t],red[t+s]); __syncthreads(); }
  float mx = red[0]; __syncthreads();
  float e = (t < D) ? expf(v - mx) : 0.f;
  red[t] = e; __syncthreads();
  for (int s=128; s>0; s>>=1){ if (t<s) red[t]+=red[t+s]; __syncthreads(); }
  float sum = red[0];
  if (t < D) g_S[i*D+t] = e / sum;
}

// U[r,i] = Wv[r,:].P[i,:] ; pb[i] = P[i,:].bv
template<int D>
__global__ void smallU(const float* __restrict__ Wv, const float* __restrict__ bv){
  int idx = blockIdx.x*256 + threadIdx.x;
  if (idx >= D*D) return;
  int rr = idx/D, i = idx%D;
  float acc = 0.f;
  for (int j=0;j<D;j++) acc += Wv[rr*D+j]*g_S[i*D+j];
  g_U[idx] = acc;
  if (idx < D){
    float a = 0.f;
    for (int j=0;j<D;j++) a += g_S[idx*D+j]*bv[j];
    g_pb[idx] = a;
  }
}

// cross = B*U + pb, scattered (fold + crop + inverse transpose) straight to output
template<int BR>
__global__ void __launch_bounds__(256) crossK(float* __restrict__ out){
  constexpr int D  = Cfg<BR>::D;
  constexpr int KT = (D + 15) / 16;
  __shared__ float Bs[16][68];
  __shared__ float Us[16][64];
  int n0 = blockIdx.x*64, m0 = blockIdx.y*64;
  int t = threadIdx.x;
  int tx = t & 15, ty = t >> 4;
  float acc[4][4];
  #pragma unroll
  for (int u=0;u<4;u++)
    #pragma unroll
    for (int v=0;v<4;v++) acc[u][v]=0.f;

  for (int kc=0; kc<KT; kc++){
    int k0 = kc*16;
    {   // stage B tile (64 m-rows x 16 k), transposed into Bs[k][m]
      int rr = t >> 2;
      int kq = (t & 3) * 4;
      #pragma unroll
      for (int u=0;u<4;u++){
        int k = k0 + kq + u;
        float b = (k < D) ? g_B[(m0+rr)*D + k] : 0.f;
        Bs[kq+u][rr] = b;
      }
    }
    {   // stage U tile (16 k x 64 n)
      int lc = t & 63, lr = t >> 6;
      #pragma unroll
      for (int s=0;s<4;s++){
        int kk = lr + 4*s;
        int k = k0 + kk;
        float uv = (k < D && n0+lc < D) ? g_U[k*D + n0 + lc] : 0.f;
        Us[kk][lc] = uv;
      }
    }
    __syncthreads();
    #pragma unroll
    for (int kk=0;kk<16;kk++){
      float4 b4 = *reinterpret_cast<const float4*>(&Bs[kk][ty*4]);
      float4 u4 = *reinterpret_cast<const float4*>(&Us[kk][tx*4]);
      float bvv[4]={b4.x,b4.y,b4.z,b4.w};
      float uvv[4]={u4.x,u4.y,u4.z,u4.w};
      #pragma unroll
      for (int u=0;u<4;u++)
        #pragma unroll
        for (int v=0;v<4;v++) acc[u][v] += bvv[u]*uvv[v];
    }
    __syncthreads();
  }

  #pragma unroll
  for (int u=0;u<4;u++){
    int m = m0 + ty*4 + u;
    int cc = m/1000, r = m%1000;
    int a0 = r/100, a1 = (r/10)%10, a2 = r%10;
    #pragma unroll
    for (int v=0;v<4;v++){
      int j = n0 + tx*4 + v;
      if (j >= D) continue;
      int b0 = j/(Cfg<BR>::W1*Cfg<BR>::W2), b1 = (j/Cfg<BR>::W2)%Cfg<BR>::W1, b2 = j%Cfg<BR>::W2;
      int z = a0*Cfg<BR>::W0 + b0 - Cfg<BR>::P0;
      int y = a1*Cfg<BR>::W1 + b1 - Cfg<BR>::P1;
      int x = a2*Cfg<BR>::W2 + b2 - Cfg<BR>::P2;
      if ((unsigned)z < (unsigned)Cfg<BR>::I0 &&
          (unsigned)y < (unsigned)Cfg<BR>::I1 &&
          (unsigned)x < (unsigned)Cfg<BR>::I2){
        out[outIndex<BR>(cc,z,y,x)] = acc[u][v] + g_pb[j];
      }
    }
  }
}

// ---------------- host orchestration ----------------

template<int BR>
static void runBranch(const float* feat, void* const* w, float* out){
  constexpr int D = Cfg<BR>::D;
  const float *Wq=(const float*)w[0], *bq=(const float*)w[1];
  const float *Wk=(const float*)w[2], *bk=(const float*)w[3];
  const float *Wv=(const float*)w[4], *bv=(const float*)w[5];

  zero_small<<<(160*160+255)/256, 256>>>();
  build_A<BR><<<(64000*D+255)/256, 256>>>();
  build_B<BR><<<(64000*D+255)/256, 256>>>(feat);

  constexpr int CHUNK = (BR==1) ? 800 : 1600;
  dim3 gg((D+63)/64, (D+63)/64, 64000/CHUNK);
  gemmG<D, CHUNK><<<gg, 256>>>();

  int nb = (D*D+255)/256;
  smallT<D><<<nb, 256>>>(Wk, bk);
  smallS<D><<<nb, 256>>>(Wq, bq, bk);
  softmaxK<D><<<D, 256>>>();
  smallU<D><<<nb, 256>>>(Wv, bv);

  dim3 gc((D+63)/64, 1000);
  crossK<BR><<<gc, 256>>>(out);
}

extern "C" void kernel_launch(void* const* d_in, const int* in_sizes, int n_in,
                              void* d_out, int out_size){
  (void)in_sizes; (void)n_in; (void)out_size;
  const float* axi   = (const float*)d_in[0];
  const float* cor   = (const float*)d_in[1];
  const float* sag   = (const float*)d_in[2];
  const float* atlas = (const float*)d_in[3];
  float* out = (float*)d_out;

  build_atlas0<<<(64000*120+255)/256, 256>>>(atlas);

  runBranch<0>(axi, d_in + 4,  out);
  runBranch<1>(cor, d_in + 10, out);
  runBranch<2>(sag, d_in + 16, out);
}

// round 3
// speedup vs baseline: 1.1235x; 1.1235x over previous
#include <cuda_runtime.h>
#include <math.h>

// ---------------------------------------------------------------------------
// C=64 channels, 10x10x10 pixel-shuffle unfold -> M = 64000 rows.
// Branch dims: axi D=140 (w=5,7,4), cor D=112 (w=4,4,7), sag D=160 (w=4,8,5).
// atlas0: 64000 x 120 (w=5,6,4), shared across branches.
// Algebra:
//   G0 = atlas0^T B (120 x D);  G[i,j] = G0[colmap(i), j]
//   S = Wq^T G Wk + (Wq^T sA) bk^T + bq (sB^T Wk + M bk)^T,  sA[i]=s0[colmap(i)]
//   P = softmax_rows(S);  cross = B (Wv P^T) + 1 (P bv)^T   (scattered to out)
// B is never materialized: B[m,j] = g_pad[ccBase(m) + mterm(m) + jterm(j)]
// ---------------------------------------------------------------------------

__device__ float g_atlas0[64000*120];
__device__ float g_pad[64000*160];     // padded, transpose-folded feat (reused per branch)
__device__ float g_G0[120*160];
__device__ float g_T[160*160];
__device__ float g_S[160*160];
__device__ float g_U[160*160];
__device__ float g_s0[120];
__device__ float g_sB[160];
__device__ float g_Z[160];
__device__ float g_pb[160];

template<int BR> struct Cfg;
// axi: internal = input (64,48,66,38); pad->(50,70,40) pb(1,2,1); w=(5,7,4); D=140
template<> struct Cfg<0>{
  static constexpr int D=140, W0=5,W1=7,W2=4, P0=1,P1=2,P2=1, I0=48,I1=66,I2=38;
  static constexpr int PS0=50,PS1=70,PS2=40, OUT0=0;
};
// cor: internal = cor.transpose(0,1,2,4,3) -> (64,38,38,66); pb(1,1,2); w=(4,4,7); D=112
template<> struct Cfg<1>{
  static constexpr int D=112, W0=4,W1=4,W2=7, P0=1,P1=1,P2=2, I0=38,I1=38,I2=66;
  static constexpr int PS0=40,PS1=40,PS2=70, OUT0=7704576;
};
// sag: internal = sag.transpose(0,1,4,3,2) -> (64,38,78,48); pb(1,1,1); w=(4,8,5); D=160
template<> struct Cfg<2>{
  static constexpr int D=160, W0=4,W1=8,W2=5, P0=1,P1=1,P2=1, I0=38,I1=78,I2=48;
  static constexpr int PS0=40,PS1=80,PS2=50, OUT0=13804032;
};

// gather from raw input, folding the branch transpose; 0 outside valid region
template<int BR>
__device__ __forceinline__ float loadFeat(const float* __restrict__ f, int cc, int z, int y, int x){
  if ((unsigned)z >= (unsigned)Cfg<BR>::I0 ||
      (unsigned)y >= (unsigned)Cfg<BR>::I1 ||
      (unsigned)x >= (unsigned)Cfg<BR>::I2) return 0.f;
  if constexpr (BR==0) return f[((cc*48+z)*66+y)*38+x];
  else if constexpr (BR==1) return f[((cc*38+z)*66+x)*38+y];
  else                      return f[((cc*48+x)*78+y)*38+z];
}

// scatter index into concatenated output, folding inverse branch transpose
template<int BR>
__device__ __forceinline__ int outIndex(int cc, int z, int y, int x){
  if constexpr (BR==0) return ((cc*48+z)*66+y)*38+x;
  else if constexpr (BR==1) return Cfg<1>::OUT0 + ((cc*38+z)*66+x)*38+y;
  else                      return Cfg<2>::OUT0 + ((cc*48+x)*78+y)*38+z;
}

// composed nearest-neighbor chain: branch spatial col -> atlas0 col (5,6,4 grid)
template<int BR>
__device__ __forceinline__ int atlasCol(int j){
  if constexpr (BR==0){
    int z=j/28, y=(j/4)%7, x=j%4;            // (5,7,4)
    int y0=(y*6)/7;
    return (z*6+y0)*4+x;
  } else if constexpr (BR==1){
    int z=j/28, y=(j/7)%4, x=j%7;            // (4,4,7) <- (5,7,4)
    int z1=(z*5)/4, y1=(y*7)/4, x1=(x*4)/7;
    int y0=(y1*6)/7;
    return (z1*6+y0)*4+x1;
  } else {
    int z=j/40, y=(j/5)%8, x=j%5;            // (4,8,5) <- (4,4,7) <- (5,7,4)
    int z2=z,  y2=y/2,     x2=(x*7)/5;
    int z1=(z2*5)/4, y1=(y2*7)/4, x1=(x2*4)/7;
    int y0=(y1*6)/7;
    return (z1*6+y0)*4+x1;
  }
}

// ---------------- kernels ----------------

__global__ void zero_small(){
  int t = blockIdx.x*256 + threadIdx.x;
  if (t < 120*160) g_G0[t] = 0.f;
  if (t < 120) g_s0[t]=0.f;
  if (t < 160) g_sB[t]=0.f;
}

__global__ void build_atlas0(const float* __restrict__ atlas){
  int idx = blockIdx.x*256 + threadIdx.x;
  if (idx >= 64000*120) return;
  int m = idx / 120, j = idx % 120;
  int cc = m / 1000, r = m % 1000;
  int a0 = r/100, a1 = (r/10)%10, a2 = r%10;
  int b0 = j/24, b1 = (j/4)%6, b2 = j%4;
  int z = a0*5 + b0 - 2, y = a1*6 + b1 - 2, x = a2*4 + b2 - 1;
  float v = 0.f;
  if ((unsigned)z < 46u && (unsigned)y < 56u && (unsigned)x < 38u)
    v = atlas[((cc*46+z)*56+y)*38+x];
  g_atlas0[idx] = v;
}

// padded, transpose-folded feat. grid = 64*PS0 blocks, block 256 looping a plane.
template<int BR>
__global__ void build_pad(const float* __restrict__ feat){
  constexpr int PS0=Cfg<BR>::PS0, PS1=Cfg<BR>::PS1, PS2=Cfg<BR>::PS2;
  int bz = blockIdx.x;
  int cc = bz / PS0, zp = bz % PS0;
  int z = zp - Cfg<BR>::P0;
  float* dst = g_pad + (size_t)bz * (PS1*PS2);
  for (int i = threadIdx.x; i < PS1*PS2; i += blockDim.x){
    int yp = i / PS2, xp = i % PS2;
    dst[i] = loadFeat<BR>(feat, cc, z, yp - Cfg<BR>::P1, xp - Cfg<BR>::P2);
  }
}

// G0 = atlas0^T B (120 x D), K split by channel (blockIdx.z = cc, 1000 rows each).
// B gathered from g_pad via separable address. Fused column sums s0, sB.
template<int BR>
__global__ void __launch_bounds__(256) gemmG0(){
  constexpr int D=Cfg<BR>::D, W0=Cfg<BR>::W0, W1=Cfg<BR>::W1, W2=Cfg<BR>::W2;
  constexpr int S1=Cfg<BR>::PS1*Cfg<BR>::PS2, S2=Cfg<BR>::PS2;
  __shared__ float As[8][64];
  __shared__ float Bs[8][64];
  __shared__ int mterm[1000];
  __shared__ int jterm[64];
  int tj0 = blockIdx.x*64, ti0 = blockIdx.y*64;
  int cc  = blockIdx.z;
  int t = threadIdx.x;

  for (int r = t; r < 1000; r += 256){
    int a0=r/100, a1=(r/10)%10, a2=r%10;
    mterm[r] = (a0*W0)*S1 + (a1*W1)*S2 + (a2*W2);
  }
  if (t < 64){
    int j = tj0 + t;
    if (j < D){
      int b0=j/(W1*W2), b1=(j/W2)%W1, b2=j%W2;
      jterm[t] = b0*S1 + b1*S2 + b2;
    } else jterm[t] = 0;
  }
  __syncthreads();

  int lc = t & 63, lr = t >> 6;    // loader lanes
  int tx = t & 15, ty = t >> 4;    // compute 4x4
  bool jok = (tj0+lc) < D;
  bool iok = (ti0+lc) < 120;
  int jt = jterm[lc];
  const float* padc = g_pad + (size_t)cc * (1000*D);
  const float* atl  = g_atlas0 + (size_t)cc * (1000*120) + ti0 + lc;

  float acc[4][4];
  #pragma unroll
  for (int u=0;u<4;u++)
    #pragma unroll
    for (int v=0;v<4;v++) acc[u][v]=0.f;
  float aCS = 0.f, bCS = 0.f;

  for (int mc = 0; mc < 1000; mc += 8){
    #pragma unroll
    for (int s=0;s<2;s++){
      int kk = lr + 4*s;
      int r = mc + kk;
      float a = iok ? atl[r*120] : 0.f;
      float b = jok ? padc[mterm[r] + jt] : 0.f;
      As[kk][lc] = a; Bs[kk][lc] = b;
      aCS += a; bCS += b;
    }
    __syncthreads();
    #pragma unroll
    for (int kk=0;kk<8;kk++){
      float4 a4 = *reinterpret_cast<const float4*>(&As[kk][ty*4]);
      float4 b4 = *reinterpret_cast<const float4*>(&Bs[kk][tx*4]);
      float av[4]={a4.x,a4.y,a4.z,a4.w};
      float bv[4]={b4.x,b4.y,b4.z,b4.w};
      #pragma unroll
      for (int u=0;u<4;u++)
        #pragma unroll
        for (int v=0;v<4;v++) acc[u][v] += av[u]*bv[v];
    }
    __syncthreads();
  }
  #pragma unroll
  for (int u=0;u<4;u++){
    int i = ti0 + ty*4 + u;
    if (i < 120){
      #pragma unroll
      for (int v=0;v<4;v++){
        int j = tj0 + tx*4 + v;
        if (j < D) atomicAdd(&g_G0[i*D+j], acc[u][v]);
      }
    }
  }
  if (blockIdx.x==0 && iok) atomicAdd(&g_s0[ti0+lc], aCS);
  if (blockIdx.y==0 && jok) atomicAdd(&g_sB[tj0+lc], bCS);
}

// T = G*Wk (G = rowgather(G0)) ; Z[j] = sB.Wk[:,j] + M*bk[j]
template<int BR>
__global__ void smallT(const float* __restrict__ Wk, const float* __restrict__ bk){
  constexpr int D = Cfg<BR>::D;
  int idx = blockIdx.x*256 + threadIdx.x;
  if (idx < D*D){
    int p = idx/D, j = idx%D;
    int gp = atlasCol<BR>(p);
    float acc = 0.f;
    for (int r=0;r<D;r++) acc += g_G0[gp*D+r]*Wk[r*D+j];
    g_T[idx] = acc;
  }
  if (idx < D){
    float z = 0.f;
    for (int r=0;r<D;r++) z += g_sB[r]*Wk[r*D+idx];
    g_Z[idx] = z + 64000.f*bk[idx];
  }
}

// S = Wq^T T + (Wq^T sA) bk^T + bq Z^T,  sA[p] = s0[colmap(p)]
template<int BR>
__global__ void smallS(const float* __restrict__ Wq, const float* __restrict__ bq,
                       const float* __restrict__ bk){
  constexpr int D = Cfg<BR>::D;
  __shared__ float sAl[160];
  int t = threadIdx.x;
  if (t < D) sAl[t] = g_s0[atlasCol<BR>(t)];
  __syncthreads();
  int idx = blockIdx.x*256 + t;
  if (idx >= D*D) return;
  int i = idx/D, j = idx%D;
  float acc = 0.f, acc2 = 0.f;
  for (int p=0;p<D;p++){
    float w = Wq[p*D+i];
    acc  += w * g_T[p*D+j];
    acc2 += w * sAl[p];
  }
  g_S[idx] = acc + acc2*bk[j] + bq[i]*g_Z[j];
}

template<int D>
__global__ void softmaxK(){
  __shared__ float red[256];
  int i = blockIdx.x, t = threadIdx.x;
  float v = (t < D) ? g_S[i*D+t] : -3.4e38f;
  red[t] = v; __syncthreads();
  for (int s=128; s>0; s>>=1){ if (t<s) red[t]=fmaxf(red[t],red[t+s]); __syncthreads(); }
  float mx = red[0]; __syncthreads();
  float e = (t < D) ? expf(v - mx) : 0.f;
  red[t] = e; __syncthreads();
  for (int s=128; s>0; s>>=1){ if (t<s) red[t]+=red[t+s]; __syncthreads(); }
  float sum = red[0];
  if (t < D) g_S[i*D+t] = e / sum;
}

// U[r,i] = Wv[r,:].P[i,:] ; pb[i] = P[i,:].bv
template<int D>
__global__ void smallU(const float* __restrict__ Wv, const float* __restrict__ bv){
  int idx = blockIdx.x*256 + threadIdx.x;
  if (idx >= D*D) return;
  int rr = idx/D, i = idx%D;
  float acc = 0.f;
  for (int j=0;j<D;j++) acc += Wv[rr*D+j]*g_S[i*D+j];
  g_U[idx] = acc;
  if (idx < D){
    float a = 0.f;
    for (int j=0;j<D;j++) a += g_S[idx*D+j]*bv[j];
    g_pb[idx] = a;
  }
}

// cross = B*U + pb, B gathered from g_pad; scatter (fold+crop+transpose) to out.
template<int BR>
__global__ void __launch_bounds__(256) crossK(float* __restrict__ out){
  constexpr int D=Cfg<BR>::D, W0=Cfg<BR>::W0, W1=Cfg<BR>::W1, W2=Cfg<BR>::W2;
  constexpr int S1=Cfg<BR>::PS1*Cfg<BR>::PS2, S2=Cfg<BR>::PS2;
  constexpr int KT = (D + 15) / 16;
  __shared__ float Bs[16][68];
  __shared__ float Us[16][64];
  __shared__ int mterm[64];
  __shared__ int jterm[160];
  int n0 = blockIdx.x*64, m0 = blockIdx.y*64;
  int t = threadIdx.x;

  if (t < 64){
    int m = m0 + t;
    int cc = m/1000, r = m%1000;
    int a0 = r/100, a1 = (r/10)%10, a2 = r%10;
    mterm[t] = cc*(1000*D) + (a0*W0)*S1 + (a1*W1)*S2 + (a2*W2);
  }
  if (t < D){
    int b0=t/(W1*W2), b1=(t/W2)%W1, b2=t%W2;
    jterm[t] = b0*S1 + b1*S2 + b2;
  }
  __syncthreads();

  int tx = t & 15, ty = t >> 4;
  float acc[4][4];
  #pragma unroll
  for (int u=0;u<4;u++)
    #pragma unroll
    for (int v=0;v<4;v++) acc[u][v]=0.f;

  for (int kc=0; kc<KT; kc++){
    int k0 = kc*16;
    {   // B tile: 64 m-rows x 16 k, transposed into Bs[k][m]
      int rr = t & 63, kg = t >> 6;
      int mt = mterm[rr];
      #pragma unroll
      for (int u=0;u<4;u++){
        int kk = kg*4 + u;
        int k = k0 + kk;
        Bs[kk][rr] = (k < D) ? g_pad[mt + jterm[k]] : 0.f;
      }
    }
    {   // U tile (16 k x 64 n)
      int lc = t & 63, lr = t >> 6;
      #pragma unroll
      for (int s=0;s<4;s++){
        int kk = lr + 4*s;
        int k = k0 + kk;
        float uv = (k < D && n0+lc < D) ? g_U[k*D + n0 + lc] : 0.f;
        Us[kk][lc] = uv;
      }
    }
    __syncthreads();
    #pragma unroll
    for (int kk=0;kk<16;kk++){
      float4 b4 = *reinterpret_cast<const float4*>(&Bs[kk][ty*4]);
      float4 u4 = *reinterpret_cast<const float4*>(&Us[kk][tx*4]);
      float bvv[4]={b4.x,b4.y,b4.z,b4.w};
      float uvv[4]={u4.x,u4.y,u4.z,u4.w};
      #pragma unroll
      for (int u=0;u<4;u++)
        #pragma unroll
        for (int v=0;v<4;v++) acc[u][v] += bvv[u]*uvv[v];
    }
    __syncthreads();
  }

  #pragma unroll
  for (int u=0;u<4;u++){
    int m = m0 + ty*4 + u;
    int cc = m/1000, r = m%1000;
    int a0 = r/100, a1 = (r/10)%10, a2 = r%10;
    #pragma unroll
    for (int v=0;v<4;v++){
      int j = n0 + tx*4 + v;
      if (j >= D) continue;
      int b0 = j/(W1*W2), b1 = (j/W2)%W1, b2 = j%W2;
      int z = a0*W0 + b0 - Cfg<BR>::P0;
      int y = a1*W1 + b1 - Cfg<BR>::P1;
      int x = a2*W2 + b2 - Cfg<BR>::P2;
      if ((unsigned)z < (unsigned)Cfg<BR>::I0 &&
          (unsigned)y < (unsigned)Cfg<BR>::I1 &&
          (unsigned)x < (unsigned)Cfg<BR>::I2){
        out[outIndex<BR>(cc,z,y,x)] = acc[u][v] + g_pb[j];
      }
    }
  }
}

// ---------------- host orchestration ----------------

template<int BR>
static void runBranch(const float* feat, void* const* w, float* out){
  constexpr int D = Cfg<BR>::D;
  const float *Wq=(const float*)w[0], *bq=(const float*)w[1];
  const float *Wk=(const float*)w[2], *bk=(const float*)w[3];
  const float *Wv=(const float*)w[4], *bv=(const float*)w[5];

  zero_small<<<(120*160+255)/256, 256>>>();
  build_pad<BR><<<64*Cfg<BR>::PS0, 256>>>(feat);

  dim3 gg((D+63)/64, 2, 64);
  gemmG0<BR><<<gg, 256>>>();

  int nb = (D*D+255)/256;
  smallT<BR><<<nb, 256>>>(Wk, bk);
  smallS<BR><<<nb, 256>>>(Wq, bq, bk);
  softmaxK<D><<<D, 256>>>();
  smallU<D><<<nb, 256>>>(Wv, bv);

  dim3 gc((D+63)/64, 1000);
  crossK<BR><<<gc, 256>>>(out);
}

extern "C" void kernel_launch(void* const* d_in, const int* in_sizes, int n_in,
                              void* d_out, int out_size){
  (void)in_sizes; (void)n_in; (void)out_size;
  const float* axi   = (const float*)d_in[0];
  const float* cor   = (const float*)d_in[1];
  const float* sag   = (const float*)d_in[2];
  const float* atlas = (const float*)d_in[3];
  float* out = (float*)d_out;

  build_atlas0<<<(64000*120+255)/256, 256>>>(atlas);

  runBranch<0>(axi, d_in + 4,  out);
  runBranch<1>(cor, d_in + 10, out);
  runBranch<2>(sag, d_in + 16, out);
}

// round 4
// speedup vs baseline: 1.2828x; 1.1418x over previous
#include <cuda_runtime.h>
#include <math.h>

// ---------------------------------------------------------------------------
// C=64 channels, 10x10x10 pixel-shuffle unfold -> M = 64000 rows.
// Branch dims: axi D=140 (w=5,7,4), cor D=112 (w=4,4,7), sag D=160 (w=4,8,5).
// atlas0: 64000 x 120 (w=5,6,4), shared across branches.
// Algebra:
//   G0 = atlas0^T B (120 x D);  G[i,j] = G0[colmap(i), j]
//   S = Wq^T G Wk + (Wq^T sA) bk^T + bq (sB^T Wk + M bk)^T,  sA[i]=s0[colmap(i)]
//   P = softmax_rows(S);  cross = B (Wv P^T) + 1 (P bv)^T   (scattered to out)
// B is never materialized: B[m,j] = g_pad[ccBase(m) + mterm(m) + jterm(j)]
// ---------------------------------------------------------------------------

#define NCH 5   // K-split chunks per channel in gemmG0 (200 rows each)

__device__ float g_atlas0[64000*120];
__device__ float g_pad[64000*160];     // padded, transpose-folded feat (reused per branch)
__device__ float g_G0p[NCH*120*160];   // split-K partial G0 slabs
__device__ float g_G0[120*160];
__device__ float g_T[160*160];
__device__ float g_S[160*160];
__device__ float g_U[160*160];
__device__ float g_s0[120];
__device__ float g_sB[160];
__device__ float g_Z[160];
__device__ float g_pb[160];

template<int BR> struct Cfg;
// axi: internal = input (64,48,66,38); pad->(50,70,40) pb(1,2,1); w=(5,7,4); D=140
template<> struct Cfg<0>{
  static constexpr int D=140, W0=5,W1=7,W2=4, P0=1,P1=2,P2=1, I0=48,I1=66,I2=38;
  static constexpr int PS0=50,PS1=70,PS2=40, OUT0=0;
};
// cor: internal = cor.transpose(0,1,2,4,3) -> (64,38,38,66); pb(1,1,2); w=(4,4,7); D=112
template<> struct Cfg<1>{
  static constexpr int D=112, W0=4,W1=4,W2=7, P0=1,P1=1,P2=2, I0=38,I1=38,I2=66;
  static constexpr int PS0=40,PS1=40,PS2=70, OUT0=7704576;
};
// sag: internal = sag.transpose(0,1,4,3,2) -> (64,38,78,48); pb(1,1,1); w=(4,8,5); D=160
template<> struct Cfg<2>{
  static constexpr int D=160, W0=4,W1=8,W2=5, P0=1,P1=1,P2=1, I0=38,I1=78,I2=48;
  static constexpr int PS0=40,PS1=80,PS2=50, OUT0=13804032;
};

// gather from raw input, folding the branch transpose; 0 outside valid region
template<int BR>
__device__ __forceinline__ float loadFeat(const float* __restrict__ f, int cc, int z, int y, int x){
  if ((unsigned)z >= (unsigned)Cfg<BR>::I0 ||
      (unsigned)y >= (unsigned)Cfg<BR>::I1 ||
      (unsigned)x >= (unsigned)Cfg<BR>::I2) return 0.f;
  if constexpr (BR==0) return f[((cc*48+z)*66+y)*38+x];
  else if constexpr (BR==1) return f[((cc*38+z)*66+x)*38+y];
  else                      return f[((cc*48+x)*78+y)*38+z];
}

// scatter index into concatenated output, folding inverse branch transpose
template<int BR>
__device__ __forceinline__ int outIndex(int cc, int z, int y, int x){
  if constexpr (BR==0) return ((cc*48+z)*66+y)*38+x;
  else if constexpr (BR==1) return Cfg<1>::OUT0 + ((cc*38+z)*66+x)*38+y;
  else                      return Cfg<2>::OUT0 + ((cc*48+x)*78+y)*38+z;
}

// composed nearest-neighbor chain: branch spatial col -> atlas0 col (5,6,4 grid)
template<int BR>
__device__ __forceinline__ int atlasCol(int j){
  if constexpr (BR==0){
    int z=j/28, y=(j/4)%7, x=j%4;            // (5,7,4)
    int y0=(y*6)/7;
    return (z*6+y0)*4+x;
  } else if constexpr (BR==1){
    int z=j/28, y=(j/7)%4, x=j%7;            // (4,4,7) <- (5,7,4)
    int z1=(z*5)/4, y1=(y*7)/4, x1=(x*4)/7;
    int y0=(y1*6)/7;
    return (z1*6+y0)*4+x1;
  } else {
    int z=j/40, y=(j/5)%8, x=j%5;            // (4,8,5) <- (4,4,7) <- (5,7,4)
    int z2=z,  y2=y/2,     x2=(x*7)/5;
    int z1=(z2*5)/4, y1=(y2*7)/4, x1=(x2*4)/7;
    int y0=(y1*6)/7;
    return (z1*6+y0)*4+x1;
  }
}

// ---------------- kernels ----------------

__global__ void zero_small(){
  int t = blockIdx.x*256 + threadIdx.x;
  if (t < NCH*120*160) g_G0p[t] = 0.f;
  if (t < 120) g_s0[t]=0.f;
  if (t < 160) g_sB[t]=0.f;
}

__global__ void build_atlas0(const float* __restrict__ atlas){
  int idx = blockIdx.x*256 + threadIdx.x;
  if (idx >= 64000*120) return;
  int m = idx / 120, j = idx % 120;
  int cc = m / 1000, r = m % 1000;
  int a0 = r/100, a1 = (r/10)%10, a2 = r%10;
  int b0 = j/24, b1 = (j/4)%6, b2 = j%4;
  int z = a0*5 + b0 - 2, y = a1*6 + b1 - 2, x = a2*4 + b2 - 1;
  float v = 0.f;
  if ((unsigned)z < 46u && (unsigned)y < 56u && (unsigned)x < 38u)
    v = atlas[((cc*46+z)*56+y)*38+x];
  g_atlas0[idx] = v;
}

// padded, transpose-folded feat. grid = 64*PS0 blocks, block 256 looping a plane.
template<int BR>
__global__ void build_pad(const float* __restrict__ feat){
  constexpr int PS0=Cfg<BR>::PS0, PS1=Cfg<BR>::PS1, PS2=Cfg<BR>::PS2;
  int bz = blockIdx.x;
  int cc = bz / PS0, zp = bz % PS0;
  int z = zp - Cfg<BR>::P0;
  float* dst = g_pad + (size_t)bz * (PS1*PS2);
  for (int i = threadIdx.x; i < PS1*PS2; i += blockDim.x){
    int yp = i / PS2, xp = i % PS2;
    dst[i] = loadFeat<BR>(feat, cc, z, yp - Cfg<BR>::P1, xp - Cfg<BR>::P2);
  }
}

// G0 = atlas0^T B (120 x D). K split 320-way: blockIdx.z = cc*NCH + chunk
// (200 rows per chunk). B gathered from g_pad via separable address.
// Ping-pong smem, one sync per 8-deep k-tile. Partials into g_G0p[chunk].
template<int BR>
__global__ void __launch_bounds__(256) gemmG0(){
  constexpr int D=Cfg<BR>::D, W0=Cfg<BR>::W0, W1=Cfg<BR>::W1, W2=Cfg<BR>::W2;
  constexpr int S1=Cfg<BR>::PS1*Cfg<BR>::PS2, S2=Cfg<BR>::PS2;
  __shared__ float As[2][8][64];
  __shared__ float Bs[2][8][64];
  __shared__ int mterm[200];
  __shared__ int jterm[64];
  int tj0 = blockIdx.x*64, ti0 = blockIdx.y*64;
  int zc = blockIdx.z;
  int cc = zc / NCH, ch = zc % NCH;
  int r0 = ch*200;
  int t = threadIdx.x;

  if (t < 200){
    int r = r0 + t;
    int a0=r/100, a1=(r/10)%10, a2=r%10;
    mterm[t] = (a0*W0)*S1 + (a1*W1)*S2 + (a2*W2);
  }
  if (t < 64){
    int j = tj0 + t;
    if (j < D){
      int b0=j/(W1*W2), b1=(j/W2)%W1, b2=j%W2;
      jterm[t] = b0*S1 + b1*S2 + b2;
    } else jterm[t] = 0;
  }
  __syncthreads();

  int lc = t & 63, lr = t >> 6;    // loader lanes: 64 cols x 4 row-groups
  int tx = t & 15, ty = t >> 4;    // compute 4x4
  bool jok = (tj0+lc) < D;
  bool iok = (ti0+lc) < 120;
  int jt = jterm[lc];
  const float* padc = g_pad + (size_t)cc * (1000*D);
  const float* atl  = g_atlas0 + (size_t)cc*(1000*120) + (size_t)r0*120 + ti0 + lc;

  float acc[4][4];
  #pragma unroll
  for (int u=0;u<4;u++)
    #pragma unroll
    for (int v=0;v<4;v++) acc[u][v]=0.f;
  float aCS = 0.f, bCS = 0.f;

  auto loadTile = [&](int it, int p){
    #pragma unroll
    for (int s=0;s<2;s++){
      int kk = lr + 4*s;
      int r = it*8 + kk;              // local row 0..199
      float a = iok ? atl[r*120] : 0.f;
      float b = jok ? padc[mterm[r] + jt] : 0.f;
      As[p][kk][lc] = a; Bs[p][kk][lc] = b;
      aCS += a; bCS += b;
    }
  };

  loadTile(0, 0);
  __syncthreads();
  int p = 0;
  for (int it = 0; it < 25; it++){
    if (it + 1 < 25) loadTile(it+1, p^1);
    #pragma unroll
    for (int kk=0;kk<8;kk++){
      float4 a4 = *reinterpret_cast<const float4*>(&As[p][kk][ty*4]);
      float4 b4 = *reinterpret_cast<const float4*>(&Bs[p][kk][tx*4]);
      float av[4]={a4.x,a4.y,a4.z,a4.w};
      float bv[4]={b4.x,b4.y,b4.z,b4.w};
      #pragma unroll
      for (int u=0;u<4;u++)
        #pragma unroll
        for (int v=0;v<4;v++) acc[u][v] += av[u]*bv[v];
    }
    __syncthreads();
    p ^= 1;
  }

  float* slab = g_G0p + ch*(120*160);
  #pragma unroll
  for (int u=0;u<4;u++){
    int i = ti0 + ty*4 + u;
    if (i < 120){
      #pragma unroll
      for (int v=0;v<4;v++){
        int j = tj0 + tx*4 + v;
        if (j < D) atomicAdd(&slab[i*D+j], acc[u][v]);
      }
    }
  }
  if (blockIdx.x==0 && iok) atomicAdd(&g_s0[ti0+lc], aCS);
  if (blockIdx.y==0 && jok) atomicAdd(&g_sB[tj0+lc], bCS);
}

// sum the NCH partial slabs into g_G0
template<int D>
__global__ void reduceG0(){
  int idx = blockIdx.x*256 + threadIdx.x;
  if (idx >= 120*D) return;
  float s = 0.f;
  #pragma unroll
  for (int c=0;c<NCH;c++) s += g_G0p[c*(120*160) + idx];
  g_G0[idx] = s;
}

// T = G*Wk (G = rowgather(G0)) ; Z[j] = sB.Wk[:,j] + M*bk[j]
template<int BR>
__global__ void smallT(const float* __restrict__ Wk, const float* __restrict__ bk){
  constexpr int D = Cfg<BR>::D;
  int idx = blockIdx.x*256 + threadIdx.x;
  if (idx < D*D){
    int p = idx/D, j = idx%D;
    int gp = atlasCol<BR>(p);
    float acc = 0.f;
    for (int r=0;r<D;r++) acc += g_G0[gp*D+r]*Wk[r*D+j];
    g_T[idx] = acc;
  }
  if (idx < D){
    float z = 0.f;
    for (int r=0;r<D;r++) z += g_sB[r]*Wk[r*D+idx];
    g_Z[idx] = z + 64000.f*bk[idx];
  }
}

// S = Wq^T T + (Wq^T sA) bk^T + bq Z^T,  sA[p] = s0[colmap(p)]
template<int BR>
__global__ void smallS(const float* __restrict__ Wq, const float* __restrict__ bq,
                       const float* __restrict__ bk){
  constexpr int D = Cfg<BR>::D;
  __shared__ float sAl[160];
  int t = threadIdx.x;
  if (t < D) sAl[t] = g_s0[atlasCol<BR>(t)];
  __syncthreads();
  int idx = blockIdx.x*256 + t;
  if (idx >= D*D) return;
  int i = idx/D, j = idx%D;
  float acc = 0.f, acc2 = 0.f;
  for (int p=0;p<D;p++){
    float w = Wq[p*D+i];
    acc  += w * g_T[p*D+j];
    acc2 += w * sAl[p];
  }
  g_S[idx] = acc + acc2*bk[j] + bq[i]*g_Z[j];
}

template<int D>
__global__ void softmaxK(){
  __shared__ float red[256];
  int i = blockIdx.x, t = threadIdx.x;
  float v = (t < D) ? g_S[i*D+t] : -3.4e38f;
  red[t] = v; __syncthreads();
  for (int s=128; s>0; s>>=1){ if (t<s) red[t]=fmaxf(red[t],red[t+s]); __syncthreads(); }
  float mx = red[0]; __syncthreads();
  float e = (t < D) ? expf(v - mx) : 0.f;
  red[t] = e; __syncthreads();
  for (int s=128; s>0; s>>=1){ if (t<s) red[t]+=red[t+s]; __syncthreads(); }
  float sum = red[0];
  if (t < D) g_S[i*D+t] = e / sum;
}

// U[r,i] = Wv[r,:].P[i,:] ; pb[i] = P[i,:].bv
template<int D>
__global__ void smallU(const float* __restrict__ Wv, const float* __restrict__ bv){
  int idx = blockIdx.x*256 + threadIdx.x;
  if (idx >= D*D) return;
  int rr = idx/D, i = idx%D;
  float acc = 0.f;
  for (int j=0;j<D;j++) acc += Wv[rr*D+j]*g_S[i*D+j];
  g_U[idx] = acc;
  if (idx < D){
    float a = 0.f;
    for (int j=0;j<D;j++) a += g_S[idx*D+j]*bv[j];
    g_pb[idx] = a;
  }
}

// cross = B*U + pb, B gathered from g_pad; scatter (fold+crop+transpose) to out.
// Ping-pong smem, one sync per 16-deep k-tile.
template<int BR>
__global__ void __launch_bounds__(256) crossK(float* __restrict__ out){
  constexpr int D=Cfg<BR>::D, W0=Cfg<BR>::W0, W1=Cfg<BR>::W1, W2=Cfg<BR>::W2;
  constexpr int S1=Cfg<BR>::PS1*Cfg<BR>::PS2, S2=Cfg<BR>::PS2;
  constexpr int KT = (D + 15) / 16;
  __shared__ float Bs[2][16][68];
  __shared__ float Us[2][16][64];
  __shared__ int mterm[64];
  __shared__ int jterm[160];
  int n0 = blockIdx.x*64, m0 = blockIdx.y*64;
  int t = threadIdx.x;

  if (t < 64){
    int m = m0 + t;
    int cc = m/1000, r = m%1000;
    int a0 = r/100, a1 = (r/10)%10, a2 = r%10;
    mterm[t] = cc*(1000*D) + (a0*W0)*S1 + (a1*W1)*S2 + (a2*W2);
  }
  if (t < D){
    int b0=t/(W1*W2), b1=(t/W2)%W1, b2=t%W2;
    jterm[t] = b0*S1 + b1*S2 + b2;
  }
  __syncthreads();

  int tx = t & 15, ty = t >> 4;
  float acc[4][4];
  #pragma unroll
  for (int u=0;u<4;u++)
    #pragma unroll
    for (int v=0;v<4;v++) acc[u][v]=0.f;

  auto loadTile = [&](int kc, int p){
    int k0 = kc*16;
    {   // B tile: 64 m-rows x 16 k, transposed into Bs[k][m]
      int rr = t & 63, kg = t >> 6;
      int mt = mterm[rr];
      #pragma unroll
      for (int u=0;u<4;u++){
        int kk = kg*4 + u;
        int k = k0 + kk;
        Bs[p][kk][rr] = (k < D) ? g_pad[mt + jterm[k]] : 0.f;
      }
    }
    {   // U tile (16 k x 64 n)
      int lc = t & 63, lr = t >> 6;
      #pragma unroll
      for (int s=0;s<4;s++){
        int kk = lr + 4*s;
        int k = k0 + kk;
        float uv = (k < D && n0+lc < D) ? g_U[k*D + n0 + lc] : 0.f;
        Us[p][kk][lc] = uv;
      }
    }
  };

  loadTile(0, 0);
  __syncthreads();
  int p = 0;
  for (int kc=0; kc<KT; kc++){
    if (kc + 1 < KT) loadTile(kc+1, p^1);
    #pragma unroll
    for (int kk=0;kk<16;kk++){
      float4 b4 = *reinterpret_cast<const float4*>(&Bs[p][kk][ty*4]);
      float4 u4 = *reinterpret_cast<const float4*>(&Us[p][kk][tx*4]);
      float bvv[4]={b4.x,b4.y,b4.z,b4.w};
      float uvv[4]={u4.x,u4.y,u4.z,u4.w};
      #pragma unroll
      for (int u=0;u<4;u++)
        #pragma unroll
        for (int v=0;v<4;v++) acc[u][v] += bvv[u]*uvv[v];
    }
    __syncthreads();
    p ^= 1;
  }

  #pragma unroll
  for (int u=0;u<4;u++){
    int m = m0 + ty*4 + u;
    int cc = m/1000, r = m%1000;
    int a0 = r/100, a1 = (r/10)%10, a2 = r%10;
    #pragma unroll
    for (int v=0;v<4;v++){
      int j = n0 + tx*4 + v;
      if (j >= D) continue;
      int b0 = j/(W1*W2), b1 = (j/W2)%W1, b2 = j%W2;
      int z = a0*W0 + b0 - Cfg<BR>::P0;
      int y = a1*W1 + b1 - Cfg<BR>::P1;
      int x = a2*W2 + b2 - Cfg<BR>::P2;
      if ((unsigned)z < (unsigned)Cfg<BR>::I0 &&
          (unsigned)y < (unsigned)Cfg<BR>::I1 &&
          (unsigned)x < (unsigned)Cfg<BR>::I2){
        out[outIndex<BR>(cc,z,y,x)] = acc[u][v] + g_pb[j];
      }
    }
  }
}

// ---------------- host orchestration ----------------

template<int BR>
static void runBranch(const float* feat, void* const* w, float* out){
  constexpr int D = Cfg<BR>::D;
  const float *Wq=(const float*)w[0], *bq=(const float*)w[1];
  const float *Wk=(const float*)w[2], *bk=(const float*)w[3];
  const float *Wv=(const float*)w[4], *bv=(const float*)w[5];

  zero_small<<<(NCH*120*160+255)/256, 256>>>();
  build_pad<BR><<<64*Cfg<BR>::PS0, 256>>>(feat);

  dim3 gg((D+63)/64, 2, 64*NCH);
  gemmG0<BR><<<gg, 256>>>();
  reduceG0<D><<<(120*D+255)/256, 256>>>();

  int nb = (D*D+255)/256;
  smallT<BR><<<nb, 256>>>(Wk, bk);
  smallS<BR><<<nb, 256>>>(Wq, bq, bk);
  softmaxK<D><<<D, 256>>>();
  smallU<D><<<nb, 256>>>(Wv, bv);

  dim3 gc((D+63)/64, 1000);
  crossK<BR><<<gc, 256>>>(out);
}

extern "C" void kernel_launch(void* const* d_in, const int* in_sizes, int n_in,
                              void* d_out, int out_size){
  (void)in_sizes; (void)n_in; (void)out_size;
  const float* axi   = (const float*)d_in[0];
  const float* cor   = (const float*)d_in[1];
  const float* sag   = (const float*)d_in[2];
  const float* atlas = (const float*)d_in[3];
  float* out = (float*)d_out;

  build_atlas0<<<(64000*120+255)/256, 256>>>(atlas);

  runBranch<0>(axi, d_in + 4,  out);
  runBranch<1>(cor, d_in + 10, out);
  runBranch<2>(sag, d_in + 16, out);
}